// round 5
// baseline (speedup 1.0000x reference)
#include <cuda_runtime.h>
#include <math.h>

// Honest per-element evaluation (fallback; only used when the zero-bound
// doesn't hold for the parameter set or for a given element).
__device__ __forceinline__ float fuzzy_eval(float x,
                                            const float* __restrict__ fd,
                                            const float* __restrict__ sigma,
                                            int nparam) {
    float s = 0.0f;
    for (int j = 0; j < nparam; j++) {
        float sg = sigma[j];
        float d  = (x - fd[j]) / (sg * sg);
        s += sqrtf(d);          // NaN if d < 0, propagates
    }
    float o = expf(-s);
    if (isnan(o)) o = x;        // reference's NaN fallback
    return o;
}

// Zero-bound: C0 = sum_j sqrt((0 - fd_j)/sigma_j^2).
// If any fd_j > 0, its term is NaN -> C0 NaN -> fast path disabled.
// Otherwise, for x >= 0 every term of s(x) is monotone increasing in x
// (fd_j <= 0 <= x), so s(x) >= C0 with all radicands >= 0 (no NaN).
// expf(-s) underflows to exactly 0.0f once s >= ~104.3; 106 adds margin.
//
// Each WARP computes the full bound redundantly (32 params/lane), so there
// is NO __syncthreads, NO shared memory, and no cross-warp dependency:
// a warp proceeds the moment its own loads complete.
__global__ void __launch_bounds__(128)
fuzzy_fused_kernel(const float4* __restrict__ x4,
                   const float* __restrict__ fd,
                   const float* __restrict__ sigma,
                   float4* __restrict__ out4,
                   int n4, int nparam) {
    const int tid  = threadIdx.x;
    const int lane = tid & 31;
    const int gid  = blockIdx.x * 128 + tid;

    // Issue the x load FIRST so its DRAM latency overlaps the reduction.
    float4 xv = make_float4(0.f, 0.f, 0.f, 0.f);
    const bool valid = (gid < n4);
    if (valid) xv = x4[gid];

    // ---- Warp-redundant bound: 4 independent accumulators for ILP ----
    float a0 = 0.f, a1 = 0.f, a2 = 0.f, a3 = 0.f;
    const int nq = nparam >> 2;                 // float4 groups (256 here)
    const float4* fd4 = (const float4*)fd;
    const float4* sg4 = (const float4*)sigma;
    for (int k = lane; k < nq; k += 32) {       // 8 iterations for nparam=1024
        float4 f = fd4[k];
        float4 g = sg4[k];
        a0 += sqrtf(__fdividef(-f.x, g.x * g.x));
        a1 += sqrtf(__fdividef(-f.y, g.y * g.y));
        a2 += sqrtf(__fdividef(-f.z, g.z * g.z));
        a3 += sqrtf(__fdividef(-f.w, g.w * g.w));
    }
    float acc = (a0 + a1) + (a2 + a3);
    // scalar remainder (nparam % 4), normally empty
    for (int j = (nq << 2) + lane; j < nparam; j += 32) {
        float g = sigma[j];
        acc += sqrtf(__fdividef(-fd[j], g * g));
    }
#pragma unroll
    for (int o = 16; o > 0; o >>= 1)
        acc += __shfl_xor_sync(0xffffffffu, acc, o);

    // NaN-safe: NaN >= 106 is false -> slow path.
    const bool fast_ok = (acc >= 106.0f);

    // ---- Apply ----
    if (!valid) return;
    float4 ov;
    ov.x = (fast_ok && xv.x >= 0.0f) ? 0.0f : fuzzy_eval(xv.x, fd, sigma, nparam);
    ov.y = (fast_ok && xv.y >= 0.0f) ? 0.0f : fuzzy_eval(xv.y, fd, sigma, nparam);
    ov.z = (fast_ok && xv.z >= 0.0f) ? 0.0f : fuzzy_eval(xv.z, fd, sigma, nparam);
    ov.w = (fast_ok && xv.w >= 0.0f) ? 0.0f : fuzzy_eval(xv.w, fd, sigma, nparam);
    out4[gid] = ov;
}

// Scalar tail kernel (only if out_size % 4 != 0; not expected for B=262144).
__global__ void fuzzy_tail_kernel(const float* __restrict__ x,
                                  const float* __restrict__ fd,
                                  const float* __restrict__ sigma,
                                  float* __restrict__ out,
                                  int start, int n, int nparam) {
    const int i = start + blockIdx.x * blockDim.x + threadIdx.x;
    if (i >= n) return;
    float C0 = 0.0f;
    for (int j = 0; j < nparam; j++) {
        float g = sigma[j];
        C0 += sqrtf(-fd[j] / (g * g));
    }
    float xv = x[i];
    out[i] = (C0 >= 106.0f && xv >= 0.0f) ? 0.0f
                                          : fuzzy_eval(xv, fd, sigma, nparam);
}

extern "C" void kernel_launch(void* const* d_in, const int* in_sizes, int n_in,
                              void* d_out, int out_size) {
    const float* x     = (const float*)d_in[0];
    const float* fd    = (const float*)d_in[1];
    const float* sigma = (const float*)d_in[2];
    float* out = (float*)d_out;

    const int n      = out_size;        // B samples
    const int nparam = in_sizes[1];     // I*O

    const int n4 = n / 4;
    if (n4 > 0) {
        const int blocks = (n4 + 127) / 128;   // 512 blocks for B=262144
        fuzzy_fused_kernel<<<blocks, 128>>>(
            (const float4*)x, fd, sigma, (float4*)out, n4, nparam);
    }
    const int tail_start = n4 * 4;
    const int tail_n = n - tail_start;
    if (tail_n > 0) {
        fuzzy_tail_kernel<<<(tail_n + 255) / 256, 256>>>(
            x, fd, sigma, out, tail_start, n, nparam);
    }
}

// round 6
// speedup vs baseline: 1.3478x; 1.3478x over previous
#include <cuda_runtime.h>
#include <math.h>

// Honest per-element evaluation (fallback; only used when the zero-bound
// doesn't hold for the parameter set or for a given element).
__device__ __forceinline__ float fuzzy_eval(float x,
                                            const float* __restrict__ fd,
                                            const float* __restrict__ sigma,
                                            int nparam) {
    float s = 0.0f;
    for (int j = 0; j < nparam; j++) {
        float sg = sigma[j];
        float d  = (x - fd[j]) / (sg * sg);
        s += sqrtf(d);          // NaN if d < 0, propagates
    }
    float o = expf(-s);
    if (isnan(o)) o = x;        // reference's NaN fallback
    return o;
}

// Zero-bound (single pass):
//   C0 = sum_j sqrt((0 - fd_j)/sigma_j^2)
// If any fd_j > 0, its term is NaN -> C0 NaN -> fast path disabled.
// Otherwise, for x >= 0 every term of s(x) is monotone increasing in x
// (fd_j <= 0 <= x), so s(x) >= C0 with all radicands >= 0 (no NaN).
// expf(-s) underflows to exactly 0.0f once s >= ~104.3; 106 adds margin.
//
// Shape: grid 256 x 256 threads, float4 per thread for x (the measured-best
// memory shape), block-level single-pass bound: each thread loads exactly
// ONE float4 of fd and ONE float4 of sigma (8 KB/block total), warp shuffle
// tree, ONE barrier, then an in-register pairwise sum of the 8 warp partials.
__global__ void __launch_bounds__(256)
fuzzy_fused_kernel(const float4* __restrict__ x4,
                   const float* __restrict__ fd,
                   const float* __restrict__ sigma,
                   float4* __restrict__ out4,
                   int n4, int nparam) {
    const int tid  = threadIdx.x;
    const int lane = tid & 31;
    const int wid  = tid >> 5;
    const int gid  = blockIdx.x * 256 + tid;

    // ---- Param loads first (earliest dependency), x load overlapped ----
    float a0 = 0.f, a1 = 0.f, a2 = 0.f, a3 = 0.f;
    const int nq = nparam >> 2;                 // float4 groups (256 here)
    const float4* fd4 = (const float4*)fd;
    const float4* sg4 = (const float4*)sigma;
    for (int k = tid; k < nq; k += 256) {       // exactly 1 iter for nparam=1024
        float4 f = fd4[k];
        float4 g = sg4[k];
        a0 += sqrtf(__fdividef(-f.x, g.x * g.x));
        a1 += sqrtf(__fdividef(-f.y, g.y * g.y));
        a2 += sqrtf(__fdividef(-f.z, g.z * g.z));
        a3 += sqrtf(__fdividef(-f.w, g.w * g.w));
    }
    float acc = (a0 + a1) + (a2 + a3);
    // scalar remainder (nparam % 4), normally empty
    for (int j = (nq << 2) + tid; j < nparam; j += 256) {
        float g = sigma[j];
        acc += sqrtf(__fdividef(-fd[j], g * g));
    }

    // x load issued here so its DRAM latency overlaps the shuffle/barrier.
    float4 xv = make_float4(0.f, 0.f, 0.f, 0.f);
    const bool valid = (gid < n4);
    if (valid) xv = x4[gid];

    __shared__ float sred[8];
#pragma unroll
    for (int o = 16; o > 0; o >>= 1)
        acc += __shfl_xor_sync(0xffffffffu, acc, o);
    if (lane == 0) sred[wid] = acc;
    __syncthreads();

    // Pairwise in-register sum of the 8 warp partials (no second barrier).
    float t0 = sred[0] + sred[1], t1 = sred[2] + sred[3];
    float t2 = sred[4] + sred[5], t3 = sred[6] + sred[7];
    float C0 = (t0 + t1) + (t2 + t3);

    // NaN-safe: NaN >= 106 is false -> slow path.
    const bool fast_ok = (C0 >= 106.0f);

    // ---- Apply ----
    if (!valid) return;
    float4 ov;
    ov.x = (fast_ok && xv.x >= 0.0f) ? 0.0f : fuzzy_eval(xv.x, fd, sigma, nparam);
    ov.y = (fast_ok && xv.y >= 0.0f) ? 0.0f : fuzzy_eval(xv.y, fd, sigma, nparam);
    ov.z = (fast_ok && xv.z >= 0.0f) ? 0.0f : fuzzy_eval(xv.z, fd, sigma, nparam);
    ov.w = (fast_ok && xv.w >= 0.0f) ? 0.0f : fuzzy_eval(xv.w, fd, sigma, nparam);
    out4[gid] = ov;
}

// Scalar tail kernel (only if out_size % 4 != 0; not expected for B=262144).
__global__ void fuzzy_tail_kernel(const float* __restrict__ x,
                                  const float* __restrict__ fd,
                                  const float* __restrict__ sigma,
                                  float* __restrict__ out,
                                  int start, int n, int nparam) {
    const int i = start + blockIdx.x * blockDim.x + threadIdx.x;
    if (i >= n) return;
    float C0 = 0.0f;
    for (int j = 0; j < nparam; j++) {
        float g = sigma[j];
        C0 += sqrtf(-fd[j] / (g * g));
    }
    float xv = x[i];
    out[i] = (C0 >= 106.0f && xv >= 0.0f) ? 0.0f
                                          : fuzzy_eval(xv, fd, sigma, nparam);
}

extern "C" void kernel_launch(void* const* d_in, const int* in_sizes, int n_in,
                              void* d_out, int out_size) {
    const float* x     = (const float*)d_in[0];
    const float* fd    = (const float*)d_in[1];
    const float* sigma = (const float*)d_in[2];
    float* out = (float*)d_out;

    const int n      = out_size;        // B samples
    const int nparam = in_sizes[1];     // I*O

    const int n4 = n / 4;
    if (n4 > 0) {
        const int blocks = (n4 + 255) / 256;   // 256 blocks for B=262144
        fuzzy_fused_kernel<<<blocks, 256>>>(
            (const float4*)x, fd, sigma, (float4*)out, n4, nparam);
    }
    const int tail_start = n4 * 4;
    const int tail_n = n - tail_start;
    if (tail_n > 0) {
        fuzzy_tail_kernel<<<(tail_n + 255) / 256, 256>>>(
            x, fd, sigma, out, tail_start, n, nparam);
    }
}